// round 5
// baseline (speedup 1.0000x reference)
#include <cuda_runtime.h>
#include <math.h>

#define NN   32768
#define EE   262144
#define FF   64
#define ZZ   10
#define NBB  8
#define LL   2
#define HH   16

#define EPSC   0.24253562503633297f
#define SQRT2C 1.4142135623730951f
#define PI_F   3.14159265358979323846f

// Scratch (device globals; allocation-free), 16B-aligned for float4 access
__device__ __align__(16) float g_sA[NN * FF];
__device__ __align__(16) float g_vA[NN * 3 * FF];
__device__ __align__(16) float g_sB[NN * FF];
__device__ __align__(16) float g_vB[NN * 3 * FF];
__device__ __align__(16) float g_aggS[NN * FF];
__device__ __align__(16) float g_aggV[NN * 3 * FF];

__device__ __forceinline__ void redAdd4(float* p, float a, float b, float c, float d) {
    asm volatile("red.global.add.v4.f32 [%0], {%1, %2, %3, %4};"
                 :: "l"(p), "f"(a), "f"(b), "f"(c), "f"(d) : "memory");
}

// ---------------------------------------------------------------------------
// Init: s = embed_s[spec], v = 0, agg = 0   (float4 wide)
// ---------------------------------------------------------------------------
__global__ void initK(const float* __restrict__ embed, const int* __restrict__ spec) {
    int i = blockIdx.x * 256 + threadIdx.x;
    if (i >= NN * FF / 4) return;
    int n  = i >> 4;
    int f4 = i & 15;
    const float4* e4 = (const float4*)embed;
    ((float4*)g_sA)[i] = e4[spec[n] * 16 + f4];
    float4 z = make_float4(0.f, 0.f, 0.f, 0.f);
    ((float4*)g_aggS)[i] = z;
#pragma unroll
    for (int k = 0; k < 3; k++) {
        ((float4*)g_vA)[(n * 3 + k) * 16 + f4]   = z;
        ((float4*)g_aggV)[(n * 3 + k) * 16 + f4] = z;
    }
}

// ---------------------------------------------------------------------------
// Edge kernel, 32 edges/block, 256 threads = 16 slots x 16 channel-groups,
// 2 edges per slot. Per-edge scalars (rb, y, indices) are computed ONCE by
// warp 0 and staged in smem (broadcast reads). Registers capped for occupancy.
// ---------------------------------------------------------------------------
template <bool FIRST>
__global__ void __launch_bounds__(256, 4) edgeK(
                      const float* __restrict__ vec,
                      const float* __restrict__ WrL,      // [8,320]
                      const int*   __restrict__ snd,
                      const int*   __restrict__ rcv,
                      const float* __restrict__ sIn,      // [N,F]
                      const float* __restrict__ vIn) {    // [N,3,F]
    __shared__ float WrS[NBB * 5 * FF];   // 10KB
    __shared__ float rbS[NBB][32];        // per-edge scaled bessel
    __shared__ float yS[3][32];           // per-edge unit vector
    __shared__ int   idxS[2][32];         // sender / receiver

    int t = threadIdx.x;
    {
        const float4* src = (const float4*)WrL;
        float4* dst = (float4*)WrS;
        for (int i = t; i < NBB * 5 * FF / 4; i += 256) dst[i] = src[i];
    }

    // Phase A: warp 0 computes per-edge scalars for the block's 32 edges
    if (t < 32) {
        int e = blockIdx.x * 32 + t;
        idxS[0][t] = snd[e];
        idxS[1][t] = rcv[e];
        float vx = vec[e * 3 + 0];
        float vy = vec[e * 3 + 1];
        float vz = vec[e * 3 + 2];
        float r  = sqrtf(vx * vx + vy * vy + vz * vz + 1e-12f);
        float rc = fmaxf(r, 1e-6f);
        float env = 0.f;
        if (r < 1.f) {
            float r2 = r * r;
            float r6 = r2 * r2 * r2;
            env = 1.f - 28.f * r6 + 48.f * r6 * r - 21.f * r6 * r2;
        }
        float scale = SQRT2C * env / rc;
        float s1, c1;
        __sincosf(PI_F * rc, &s1, &c1);
        float c2 = 2.f * c1;
        float sp = s1, spp = 0.f;
        rbS[0][t] = s1 * scale;
#pragma unroll
        for (int n = 1; n < NBB; n++) {
            float sn = c2 * sp - spp;
            rbS[n][t] = sn * scale;
            spp = sp; sp = sn;
        }
        float iy = 1.f / r;
        yS[0][t] = vx * iy; yS[1][t] = vy * iy; yS[2][t] = vz * iy;
    }
    __syncthreads();

    int slot = t >> 4;
    int fi   = t & 15;                    // channels 4*fi .. 4*fi+3
    int e0   = slot * 2;                  // local edge index, this slot's pair

    // Radial-weight sweep, amortized over both edges of the pair.
    const int NP = FIRST ? 2 : 5;
    float4 w[2][5];
#pragma unroll
    for (int u = 0; u < 2; u++)
#pragma unroll
        for (int p = 0; p < 5; p++) w[u][p] = make_float4(0.f, 0.f, 0.f, 0.f);

#pragma unroll
    for (int n = 0; n < NBB; n++) {
        float r0 = rbS[n][e0];
        float r1 = rbS[n][e0 + 1];
#pragma unroll
        for (int pi = 0; pi < NP; pi++) {
            int p = FIRST ? (pi * 2) : pi;
            float4 ww = *(const float4*)&WrS[n * 320 + p * 64 + fi * 4];
            float4* w0 = &w[0][FIRST ? pi : p];
            float4* w1 = &w[1][FIRST ? pi : p];
            w0->x = fmaf(r0, ww.x, w0->x); w0->y = fmaf(r0, ww.y, w0->y);
            w0->z = fmaf(r0, ww.z, w0->z); w0->w = fmaf(r0, ww.w, w0->w);
            w1->x = fmaf(r1, ww.x, w1->x); w1->y = fmaf(r1, ww.y, w1->y);
            w1->z = fmaf(r1, ww.z, w1->z); w1->w = fmaf(r1, ww.w, w1->w);
        }
    }

    // Messages + scatter
#pragma unroll
    for (int u = 0; u < 2; u++) {
        int le = e0 + u;
        int s_ = idxS[0][le];
        int r_ = idxS[1][le];
        float y0 = yS[0][le], y1 = yS[1][le], y2 = yS[2][le];
        float4 ss = *(const float4*)&sIn[s_ * FF + fi * 4];

        float4 m0, m1x, m1y, m1z;
        if (FIRST) {
#pragma unroll
            for (int c = 0; c < 4; c++) {
                float SS = (&ss.x)[c];
                (&m0.x)[c]  = (&w[u][0].x)[c] * SS;       // path 0
                float cc    = (&w[u][1].x)[c] * SS;       // path 2
                (&m1x.x)[c] = cc * y0;
                (&m1y.x)[c] = cc * y1;
                (&m1z.x)[c] = cc * y2;
            }
        } else {
            float4 vsx = *(const float4*)&vIn[(s_ * 3 + 0) * FF + fi * 4];
            float4 vsy = *(const float4*)&vIn[(s_ * 3 + 1) * FF + fi * 4];
            float4 vsz = *(const float4*)&vIn[(s_ * 3 + 2) * FF + fi * 4];
#pragma unroll
            for (int c = 0; c < 4; c++) {
                float VX = (&vsx.x)[c], VY = (&vsy.x)[c], VZ = (&vsz.x)[c];
                float SS = (&ss.x)[c];
                float w0 = (&w[u][0].x)[c], w1 = (&w[u][1].x)[c], w2 = (&w[u][2].x)[c];
                float w3 = (&w[u][3].x)[c], w4 = (&w[u][4].x)[c];
                float dot = VX * y0 + VY * y1 + VZ * y2;
                (&m0.x)[c]  = w0 * SS + w1 * dot;
                float cc = w2 * SS;
                (&m1x.x)[c] = cc * y0 + w3 * VX + w4 * (VY * y2 - VZ * y1);
                (&m1y.x)[c] = cc * y1 + w3 * VY + w4 * (VZ * y0 - VX * y2);
                (&m1z.x)[c] = cc * y2 + w3 * VZ + w4 * (VX * y1 - VY * y0);
            }
        }

        redAdd4(&g_aggS[r_ * FF + fi * 4], m0.x, m0.y, m0.z, m0.w);
        redAdd4(&g_aggV[(r_ * 3 + 0) * FF + fi * 4], m1x.x, m1x.y, m1x.z, m1x.w);
        redAdd4(&g_aggV[(r_ * 3 + 1) * FF + fi * 4], m1y.x, m1y.y, m1y.z, m1y.w);
        redAdd4(&g_aggV[(r_ * 3 + 2) * FF + fi * 4], m1z.x, m1z.y, m1z.z, m1z.w);
    }
}

// ---------------------------------------------------------------------------
// Node kernel: 16 nodes/block x 16 threads/node (4 channels each, float4)
// ---------------------------------------------------------------------------
template <int LAYER>
__global__ void nodeK(const float* __restrict__ sOld,
                      const float* __restrict__ vOld,
                      float* __restrict__ sNew,
                      float* __restrict__ vNew,
                      const int*   __restrict__ spec,
                      const float* __restrict__ WlsL,
                      const float* __restrict__ WlvL,
                      const float* __restrict__ pwL,    // [Z,9,F]
                      const float* __restrict__ WpsL,
                      const float* __restrict__ WpvL,
                      const float* __restrict__ skipS,  // [Z,F,F]
                      const float* __restrict__ skipV,
                      const float* __restrict__ Wread0,
                      const float* __restrict__ Wr1a,   // [F,H]
                      const float* __restrict__ Wr1b,   // [H]
                      float* __restrict__ out) {
    extern __shared__ float sm[];
    float* Wb0 = sm;                 // 4096
    float* Wb1 = sm + 4096;          // 4096
    float* A_s = sm + 8192;          // 1024
    float* A_v = sm + 9216;          // 3072
    float* B_s = sm + 12288;         // 1024
    float* B_v = sm + 13312;         // 3072  (total 16384 floats = 64KB)

    int t  = threadIdx.x;
    int nl = t >> 4;
    int fi = t & 15;
    int n  = blockIdx.x * 16 + nl;

    {
        const float4* a4 = (const float4*)WlsL;
        const float4* b4 = (const float4*)WlvL;
        float4* d0 = (float4*)Wb0;
        float4* d1 = (float4*)Wb1;
        for (int i = t; i < 1024; i += 256) { d0[i] = a4[i]; d1[i] = b4[i]; }
    }
    {
        float4 a = ((const float4*)g_aggS)[n * 16 + fi];
        a.x *= EPSC; a.y *= EPSC; a.z *= EPSC; a.w *= EPSC;
        *(float4*)&A_s[nl * 64 + fi * 4] = a;
#pragma unroll
        for (int k = 0; k < 3; k++) {
            float4 v = ((const float4*)g_aggV)[(n * 3 + k) * 16 + fi];
            v.x *= EPSC; v.y *= EPSC; v.z *= EPSC; v.w *= EPSC;
            *(float4*)&A_v[(nl * 3 + k) * 64 + fi * 4] = v;
        }
        float4 z = make_float4(0.f, 0.f, 0.f, 0.f);
        if (LAYER == 0) {
            ((float4*)g_aggS)[n * 16 + fi] = z;
#pragma unroll
            for (int k = 0; k < 3; k++) ((float4*)g_aggV)[(n * 3 + k) * 16 + fi] = z;
        }
        if (LAYER > 0) {
            *(float4*)&B_s[nl * 64 + fi * 4] = ((const float4*)sOld)[n * 16 + fi];
#pragma unroll
            for (int k = 0; k < 3; k++)
                *(float4*)&B_v[(nl * 3 + k) * 64 + fi * 4] =
                    ((const float4*)vOld)[(n * 3 + k) * 16 + fi];
        }
    }
    __syncthreads();

    float4 s2  = make_float4(0.f, 0.f, 0.f, 0.f);
    float4 v2x = s2, v2y = s2, v2z = s2;
#pragma unroll 4
    for (int j = 0; j < FF; j++) {
        float a  = A_s[nl * 64 + j];
        float ax = A_v[(nl * 3 + 0) * 64 + j];
        float ay = A_v[(nl * 3 + 1) * 64 + j];
        float az = A_v[(nl * 3 + 2) * 64 + j];
        float4 wls = *(const float4*)&Wb0[j * 64 + fi * 4];
        float4 wlv = *(const float4*)&Wb1[j * 64 + fi * 4];
        s2.x  = fmaf(a, wls.x, s2.x);   s2.y  = fmaf(a, wls.y, s2.y);
        s2.z  = fmaf(a, wls.z, s2.z);   s2.w  = fmaf(a, wls.w, s2.w);
        v2x.x = fmaf(ax, wlv.x, v2x.x); v2x.y = fmaf(ax, wlv.y, v2x.y);
        v2x.z = fmaf(ax, wlv.z, v2x.z); v2x.w = fmaf(ax, wlv.w, v2x.w);
        v2y.x = fmaf(ay, wlv.x, v2y.x); v2y.y = fmaf(ay, wlv.y, v2y.y);
        v2y.z = fmaf(ay, wlv.z, v2y.z); v2y.w = fmaf(ay, wlv.w, v2y.w);
        v2z.x = fmaf(az, wlv.x, v2z.x); v2z.y = fmaf(az, wlv.y, v2z.y);
        v2z.z = fmaf(az, wlv.z, v2z.z); v2z.w = fmaf(az, wlv.w, v2z.w);
    }

    int z = spec[n];

    float4 scS  = make_float4(0.f, 0.f, 0.f, 0.f);
    float4 scVx = scS, scVy = scS, scVz = scS;
    if (LAYER > 0) {
        const float* Ss = skipS + z * FF * FF;
        const float* Sv = skipV + z * FF * FF;
#pragma unroll 4
        for (int j = 0; j < FF; j++) {
            float b  = B_s[nl * 64 + j];
            float bx = B_v[(nl * 3 + 0) * 64 + j];
            float by = B_v[(nl * 3 + 1) * 64 + j];
            float bz = B_v[(nl * 3 + 2) * 64 + j];
            float4 aa = *(const float4*)&Ss[j * 64 + fi * 4];
            float4 bb = *(const float4*)&Sv[j * 64 + fi * 4];
            scS.x  = fmaf(b, aa.x, scS.x);   scS.y  = fmaf(b, aa.y, scS.y);
            scS.z  = fmaf(b, aa.z, scS.z);   scS.w  = fmaf(b, aa.w, scS.w);
            scVx.x = fmaf(bx, bb.x, scVx.x); scVx.y = fmaf(bx, bb.y, scVx.y);
            scVx.z = fmaf(bx, bb.z, scVx.z); scVx.w = fmaf(bx, bb.w, scVx.w);
            scVy.x = fmaf(by, bb.x, scVy.x); scVy.y = fmaf(by, bb.y, scVy.y);
            scVy.z = fmaf(by, bb.z, scVy.z); scVy.w = fmaf(by, bb.w, scVy.w);
            scVz.x = fmaf(bz, bb.x, scVz.x); scVz.y = fmaf(bz, bb.y, scVz.y);
            scVz.z = fmaf(bz, bb.z, scVz.z); scVz.w = fmaf(bz, bb.w, scVz.w);
        }
    }

    const float* pp = pwL + z * 9 * FF;
    float4 P[9];
#pragma unroll
    for (int k = 0; k < 9; k++) P[k] = *(const float4*)&pp[k * FF + fi * 4];
    float4 ps, pvx, pvy, pvz;
#pragma unroll
    for (int c = 0; c < 4; c++) {
        float S  = (&s2.x)[c];
        float VX = (&v2x.x)[c], VY = (&v2y.x)[c], VZ = (&v2z.x)[c];
        float vv = VX * VX + VY * VY + VZ * VZ;
        float S2 = S * S;
        float psv = (&P[0].x)[c] * S + (&P[1].x)[c] * S2 + (&P[2].x)[c] * vv
                  + (&P[3].x)[c] * S2 * S + (&P[4].x)[c] * S * vv;
        float pf  = (&P[5].x)[c] + (&P[6].x)[c] * S + (&P[7].x)[c] * S2 + (&P[8].x)[c] * vv;
        (&ps.x)[c]  = psv;
        (&pvx.x)[c] = pf * VX;
        (&pvy.x)[c] = pf * VY;
        (&pvz.x)[c] = pf * VZ;
    }
    __syncthreads();

    {
        const float4* a4 = (const float4*)WpsL;
        const float4* b4 = (const float4*)WpvL;
        float4* d0 = (float4*)Wb0;
        float4* d1 = (float4*)Wb1;
        for (int i = t; i < 1024; i += 256) { d0[i] = a4[i]; d1[i] = b4[i]; }
    }
    *(float4*)&A_s[nl * 64 + fi * 4] = ps;
    *(float4*)&A_v[(nl * 3 + 0) * 64 + fi * 4] = pvx;
    *(float4*)&A_v[(nl * 3 + 1) * 64 + fi * 4] = pvy;
    *(float4*)&A_v[(nl * 3 + 2) * 64 + fi * 4] = pvz;
    __syncthreads();

    float4 sN  = scS;
    float4 vNx = scVx, vNy = scVy, vNz = scVz;
#pragma unroll 4
    for (int j = 0; j < FF; j++) {
        float a  = A_s[nl * 64 + j];
        float ax = A_v[(nl * 3 + 0) * 64 + j];
        float ay = A_v[(nl * 3 + 1) * 64 + j];
        float az = A_v[(nl * 3 + 2) * 64 + j];
        float4 wps = *(const float4*)&Wb0[j * 64 + fi * 4];
        float4 wpv = *(const float4*)&Wb1[j * 64 + fi * 4];
        sN.x  = fmaf(a, wps.x, sN.x);   sN.y  = fmaf(a, wps.y, sN.y);
        sN.z  = fmaf(a, wps.z, sN.z);   sN.w  = fmaf(a, wps.w, sN.w);
        vNx.x = fmaf(ax, wpv.x, vNx.x); vNx.y = fmaf(ax, wpv.y, vNx.y);
        vNx.z = fmaf(ax, wpv.z, vNx.z); vNx.w = fmaf(ax, wpv.w, vNx.w);
        vNy.x = fmaf(ay, wpv.x, vNy.x); vNy.y = fmaf(ay, wpv.y, vNy.y);
        vNy.z = fmaf(ay, wpv.z, vNy.z); vNy.w = fmaf(ay, wpv.w, vNy.w);
        vNz.x = fmaf(az, wpv.x, vNz.x); vNz.y = fmaf(az, wpv.y, vNz.y);
        vNz.z = fmaf(az, wpv.z, vNz.z); vNz.w = fmaf(az, wpv.w, vNz.w);
    }

    if (LAYER < LL - 1) {
        ((float4*)sNew)[n * 16 + fi] = sN;
        ((float4*)vNew)[(n * 3 + 0) * 16 + fi] = vNx;
        ((float4*)vNew)[(n * 3 + 1) * 16 + fi] = vNy;
        ((float4*)vNew)[(n * 3 + 2) * 16 + fi] = vNz;
    }

    if (LAYER == 0) {
        float4 wr = *(const float4*)&Wread0[fi * 4];
        float part = sN.x * wr.x + sN.y * wr.y + sN.z * wr.z + sN.w * wr.w;
#pragma unroll
        for (int o = 8; o > 0; o >>= 1)
            part += __shfl_xor_sync(0xffffffffu, part, o);
        if (fi == 0) out[n * LL + 0] = part;
    } else {
        *(float4*)&B_s[nl * 64 + fi * 4] = sN;
        __syncthreads();
        int h = fi;
        float a = 0.f;
#pragma unroll 8
        for (int g = 0; g < FF; g++)
            a = fmaf(B_s[nl * 64 + g], Wr1a[g * HH + h], a);
        float sil = a / (1.f + __expf(-a));
        float part = sil * Wr1b[h];
#pragma unroll
        for (int o = 8; o > 0; o >>= 1)
            part += __shfl_xor_sync(0xffffffffu, part, o);
        if (fi == 0) out[n * LL + (LL - 1)] = part;
    }
}

// ---------------------------------------------------------------------------
extern "C" void kernel_launch(void* const* d_in, const int* in_sizes, int n_in,
                              void* d_out, int out_size) {
    const float* vectors = (const float*)d_in[0];
    const float* embed_s = (const float*)d_in[1];
    const float* Wr      = (const float*)d_in[2];
    const float* Wls     = (const float*)d_in[3];
    const float* Wlv     = (const float*)d_in[4];
    const float* skip_s  = (const float*)d_in[5];
    const float* skip_v  = (const float*)d_in[6];
    const float* pw      = (const float*)d_in[7];
    const float* Wps     = (const float*)d_in[8];
    const float* Wpv     = (const float*)d_in[9];
    const float* Wread0  = (const float*)d_in[10];
    const float* Wr1a    = (const float*)d_in[11];
    const float* Wr1b    = (const float*)d_in[12];
    const int*   senders   = (const int*)d_in[13];
    const int*   receivers = (const int*)d_in[14];
    const int*   species   = (const int*)d_in[15];
    float* out = (float*)d_out;

    void *p_sA, *p_vA, *p_sB, *p_vB;
    cudaGetSymbolAddress(&p_sA, g_sA);
    cudaGetSymbolAddress(&p_vA, g_vA);
    cudaGetSymbolAddress(&p_sB, g_sB);
    cudaGetSymbolAddress(&p_vB, g_vB);
    float* sA = (float*)p_sA;
    float* vA = (float*)p_vA;
    float* sB = (float*)p_sB;
    float* vB = (float*)p_vB;

    const int NODE_SMEM = 16384 * 4;  // 64KB
    static bool attrSet = false;
    if (!attrSet) {
        cudaFuncSetAttribute(nodeK<0>, cudaFuncAttributeMaxDynamicSharedMemorySize, NODE_SMEM);
        cudaFuncSetAttribute(nodeK<1>, cudaFuncAttributeMaxDynamicSharedMemorySize, NODE_SMEM);
        attrSet = true;
    }

    initK<<<(NN * FF / 4 + 255) / 256, 256>>>(embed_s, species);

    // ---- Layer 0 ----
    edgeK<true><<<EE / 32, 256>>>(vectors, Wr, senders, receivers, sA, vA);
    nodeK<0><<<NN / 16, 256, NODE_SMEM>>>(sA, vA, sB, vB, species,
                              Wls, Wlv, pw, Wps, Wpv,
                              skip_s, skip_v, Wread0, Wr1a, Wr1b, out);

    // ---- Layer 1 ----
    edgeK<false><<<EE / 32, 256>>>(vectors, Wr + NBB * 5 * FF, senders, receivers, sB, vB);
    nodeK<1><<<NN / 16, 256, NODE_SMEM>>>(sB, vB, sA, vA, species,
                              Wls + FF * FF, Wlv + FF * FF,
                              pw + ZZ * 9 * FF,
                              Wps + FF * FF, Wpv + FF * FF,
                              skip_s, skip_v, Wread0, Wr1a, Wr1b, out);
}

// round 6
// speedup vs baseline: 1.0011x; 1.0011x over previous
#include <cuda_runtime.h>
#include <math.h>

#define NN   32768
#define EE   262144
#define FF   64
#define ZZ   10
#define NBB  8
#define LL   2
#define HH   16

#define EPSC   0.24253562503633297f
#define SQRT2C 1.4142135623730951f
#define PI_F   3.14159265358979323846f

// Scratch (device globals; allocation-free), 16B-aligned for float4 access
__device__ __align__(16) float g_sA[NN * FF];
__device__ __align__(16) float g_vA[NN * 3 * FF];
__device__ __align__(16) float g_sB[NN * FF];
__device__ __align__(16) float g_vB[NN * 3 * FF];
__device__ __align__(16) float g_aggS[NN * FF];
__device__ __align__(16) float g_aggV[NN * 3 * FF];

__device__ __forceinline__ void redAdd1(float* p, float v) {
    asm volatile("red.global.add.f32 [%0], %1;" :: "l"(p), "f"(v) : "memory");
}

// ---------------------------------------------------------------------------
// Init: s = embed_s[spec], v = 0, agg = 0   (float4 wide)
// ---------------------------------------------------------------------------
__global__ void initK(const float* __restrict__ embed, const int* __restrict__ spec) {
    int i = blockIdx.x * 256 + threadIdx.x;
    if (i >= NN * FF / 4) return;
    int n  = i >> 4;
    int f4 = i & 15;
    const float4* e4 = (const float4*)embed;
    ((float4*)g_sA)[i] = e4[spec[n] * 16 + f4];
    float4 z = make_float4(0.f, 0.f, 0.f, 0.f);
    ((float4*)g_aggS)[i] = z;
#pragma unroll
    for (int k = 0; k < 3; k++) {
        ((float4*)g_vA)[(n * 3 + k) * 16 + f4]   = z;
        ((float4*)g_aggV)[(n * 3 + k) * 16 + f4] = z;
    }
}

// ---------------------------------------------------------------------------
// Per-edge scalar staging: bessel basis, unit vector, indices
// ---------------------------------------------------------------------------
__device__ __forceinline__ void stageEdge(
        float (*rb)[32], float (*yv)[32], int* sS, int* rS,
        const float* __restrict__ vec,
        const int* __restrict__ snd, const int* __restrict__ rcv,
        int e, int lane) {
    sS[lane] = snd[e];
    rS[lane] = rcv[e];
    float vx = vec[e * 3 + 0];
    float vy = vec[e * 3 + 1];
    float vz = vec[e * 3 + 2];
    float r  = sqrtf(vx * vx + vy * vy + vz * vz + 1e-12f);
    float rc = fmaxf(r, 1e-6f);
    float env = 0.f;
    if (r < 1.f) {
        float r2 = r * r;
        float r6 = r2 * r2 * r2;
        env = 1.f - 28.f * r6 + 48.f * r6 * r - 21.f * r6 * r2;
    }
    float scale = SQRT2C * env / rc;
    float s1, c1;
    __sincosf(PI_F * rc, &s1, &c1);
    float c2 = 2.f * c1;
    float sp = s1, spp = 0.f;
    rb[0][lane] = s1 * scale;
#pragma unroll
    for (int n = 1; n < NBB; n++) {
        float sn = c2 * sp - spp;
        rb[n][lane] = sn * scale;
        spp = sp; sp = sn;
    }
    float iy = 1.f / r;
    yv[0][lane] = vx * iy; yv[1][lane] = vy * iy; yv[2][lane] = vz * iy;
}

// ---------------------------------------------------------------------------
// Edge kernel v3: 256 threads = 64 channels x 4 edge-lanes.
// Each thread holds its channel's Wr slice in REGISTERS (no per-edge LDS sweep).
// Block processes 128 edges, staged 32 at a time (double buffered); each
// edge-lane consumes 8 edges per stage. rb/y reads are warp-broadcast LDS.
// ---------------------------------------------------------------------------
template <bool FIRST>
__global__ void __launch_bounds__(256) edgeK(
                      const float* __restrict__ vec,
                      const float* __restrict__ WrL,      // [8,320]
                      const int*   __restrict__ snd,
                      const int*   __restrict__ rcv,
                      const float* __restrict__ sIn,      // [N,F]
                      const float* __restrict__ vIn) {    // [N,3,F]
    const int NP = FIRST ? 2 : 5;
    __shared__ float rbS[2][NBB][32];
    __shared__ float yS[2][3][32];
    __shared__ int   sndS[2][32];
    __shared__ int   rcvS[2][32];

    int t  = threadIdx.x;
    int f  = t & 63;
    int el = t >> 6;

    // Wr slice for this channel, in registers (amortized over 128 edges)
    float wreg[NBB][FIRST ? 2 : 5];
#pragma unroll
    for (int n = 0; n < NBB; n++)
#pragma unroll
        for (int pi = 0; pi < NP; pi++) {
            int p = FIRST ? pi * 2 : pi;    // layer-0: only paths 0 and 2
            wreg[n][pi] = WrL[n * 320 + p * 64 + f];
        }

    int base = blockIdx.x * 128;

    if (t < 32)
        stageEdge(rbS[0], yS[0], sndS[0], rcvS[0], vec, snd, rcv, base + t, t);
    __syncthreads();

#pragma unroll
    for (int s = 0; s < 4; s++) {
        int buf = s & 1;
        if (s < 3 && t < 32)
            stageEdge(rbS[buf ^ 1], yS[buf ^ 1], sndS[buf ^ 1], rcvS[buf ^ 1],
                      vec, snd, rcv, base + (s + 1) * 32 + t, t);

        int e0 = el * 8;
#pragma unroll 2
        for (int le = 0; le < 8; le++) {
            int li = e0 + le;
            int s_ = sndS[buf][li];
            int r_ = rcvS[buf][li];

            // w[p] = sum_n rb[n] * wreg[n][p]  (rb: warp-broadcast LDS)
            float w[5];
#pragma unroll
            for (int pi = 0; pi < NP; pi++) w[pi] = 0.f;
#pragma unroll
            for (int n = 0; n < NBB; n++) {
                float rn = rbS[buf][n][li];
#pragma unroll
                for (int pi = 0; pi < NP; pi++)
                    w[pi] = fmaf(rn, wreg[n][pi], w[pi]);
            }

            float y0 = yS[buf][0][li];
            float y1 = yS[buf][1][li];
            float y2 = yS[buf][2][li];
            float ss = sIn[s_ * FF + f];

            float m0, m1x, m1y, m1z;
            if (FIRST) {
                m0 = w[0] * ss;
                float cc = w[1] * ss;           // path 2 weight
                m1x = cc * y0; m1y = cc * y1; m1z = cc * y2;
            } else {
                float vsx = vIn[(s_ * 3 + 0) * FF + f];
                float vsy = vIn[(s_ * 3 + 1) * FF + f];
                float vsz = vIn[(s_ * 3 + 2) * FF + f];
                float dot = vsx * y0 + vsy * y1 + vsz * y2;
                m0 = w[0] * ss + w[1] * dot;
                float cc = w[2] * ss;
                m1x = cc * y0 + w[3] * vsx + w[4] * (vsy * y2 - vsz * y1);
                m1y = cc * y1 + w[3] * vsy + w[4] * (vsz * y0 - vsx * y2);
                m1z = cc * y2 + w[3] * vsz + w[4] * (vsx * y1 - vsy * y0);
            }

            redAdd1(&g_aggS[r_ * FF + f], m0);
            redAdd1(&g_aggV[(r_ * 3 + 0) * FF + f], m1x);
            redAdd1(&g_aggV[(r_ * 3 + 1) * FF + f], m1y);
            redAdd1(&g_aggV[(r_ * 3 + 2) * FF + f], m1z);
        }
        __syncthreads();
    }
}

// ---------------------------------------------------------------------------
// Node kernel: 16 nodes/block x 16 threads/node (4 channels each, float4)
// ---------------------------------------------------------------------------
template <int LAYER>
__global__ void nodeK(const float* __restrict__ sOld,
                      const float* __restrict__ vOld,
                      float* __restrict__ sNew,
                      float* __restrict__ vNew,
                      const int*   __restrict__ spec,
                      const float* __restrict__ WlsL,
                      const float* __restrict__ WlvL,
                      const float* __restrict__ pwL,    // [Z,9,F]
                      const float* __restrict__ WpsL,
                      const float* __restrict__ WpvL,
                      const float* __restrict__ skipS,  // [Z,F,F]
                      const float* __restrict__ skipV,
                      const float* __restrict__ Wread0,
                      const float* __restrict__ Wr1a,   // [F,H]
                      const float* __restrict__ Wr1b,   // [H]
                      float* __restrict__ out) {
    extern __shared__ float sm[];
    float* Wb0 = sm;                 // 4096
    float* Wb1 = sm + 4096;          // 4096
    float* A_s = sm + 8192;          // 1024
    float* A_v = sm + 9216;          // 3072
    float* B_s = sm + 12288;         // 1024
    float* B_v = sm + 13312;         // 3072  (total 16384 floats = 64KB)

    int t  = threadIdx.x;
    int nl = t >> 4;
    int fi = t & 15;
    int n  = blockIdx.x * 16 + nl;

    {
        const float4* a4 = (const float4*)WlsL;
        const float4* b4 = (const float4*)WlvL;
        float4* d0 = (float4*)Wb0;
        float4* d1 = (float4*)Wb1;
        for (int i = t; i < 1024; i += 256) { d0[i] = a4[i]; d1[i] = b4[i]; }
    }
    {
        float4 a = ((const float4*)g_aggS)[n * 16 + fi];
        a.x *= EPSC; a.y *= EPSC; a.z *= EPSC; a.w *= EPSC;
        *(float4*)&A_s[nl * 64 + fi * 4] = a;
#pragma unroll
        for (int k = 0; k < 3; k++) {
            float4 v = ((const float4*)g_aggV)[(n * 3 + k) * 16 + fi];
            v.x *= EPSC; v.y *= EPSC; v.z *= EPSC; v.w *= EPSC;
            *(float4*)&A_v[(nl * 3 + k) * 64 + fi * 4] = v;
        }
        float4 z = make_float4(0.f, 0.f, 0.f, 0.f);
        if (LAYER == 0) {
            ((float4*)g_aggS)[n * 16 + fi] = z;
#pragma unroll
            for (int k = 0; k < 3; k++) ((float4*)g_aggV)[(n * 3 + k) * 16 + fi] = z;
        }
        if (LAYER > 0) {
            *(float4*)&B_s[nl * 64 + fi * 4] = ((const float4*)sOld)[n * 16 + fi];
#pragma unroll
            for (int k = 0; k < 3; k++)
                *(float4*)&B_v[(nl * 3 + k) * 64 + fi * 4] =
                    ((const float4*)vOld)[(n * 3 + k) * 16 + fi];
        }
    }
    __syncthreads();

    float4 s2  = make_float4(0.f, 0.f, 0.f, 0.f);
    float4 v2x = s2, v2y = s2, v2z = s2;
#pragma unroll 4
    for (int j = 0; j < FF; j++) {
        float a  = A_s[nl * 64 + j];
        float ax = A_v[(nl * 3 + 0) * 64 + j];
        float ay = A_v[(nl * 3 + 1) * 64 + j];
        float az = A_v[(nl * 3 + 2) * 64 + j];
        float4 wls = *(const float4*)&Wb0[j * 64 + fi * 4];
        float4 wlv = *(const float4*)&Wb1[j * 64 + fi * 4];
        s2.x  = fmaf(a, wls.x, s2.x);   s2.y  = fmaf(a, wls.y, s2.y);
        s2.z  = fmaf(a, wls.z, s2.z);   s2.w  = fmaf(a, wls.w, s2.w);
        v2x.x = fmaf(ax, wlv.x, v2x.x); v2x.y = fmaf(ax, wlv.y, v2x.y);
        v2x.z = fmaf(ax, wlv.z, v2x.z); v2x.w = fmaf(ax, wlv.w, v2x.w);
        v2y.x = fmaf(ay, wlv.x, v2y.x); v2y.y = fmaf(ay, wlv.y, v2y.y);
        v2y.z = fmaf(ay, wlv.z, v2y.z); v2y.w = fmaf(ay, wlv.w, v2y.w);
        v2z.x = fmaf(az, wlv.x, v2z.x); v2z.y = fmaf(az, wlv.y, v2z.y);
        v2z.z = fmaf(az, wlv.z, v2z.z); v2z.w = fmaf(az, wlv.w, v2z.w);
    }

    int z = spec[n];

    float4 scS  = make_float4(0.f, 0.f, 0.f, 0.f);
    float4 scVx = scS, scVy = scS, scVz = scS;
    if (LAYER > 0) {
        const float* Ss = skipS + z * FF * FF;
        const float* Sv = skipV + z * FF * FF;
#pragma unroll 4
        for (int j = 0; j < FF; j++) {
            float b  = B_s[nl * 64 + j];
            float bx = B_v[(nl * 3 + 0) * 64 + j];
            float by = B_v[(nl * 3 + 1) * 64 + j];
            float bz = B_v[(nl * 3 + 2) * 64 + j];
            float4 aa = *(const float4*)&Ss[j * 64 + fi * 4];
            float4 bb = *(const float4*)&Sv[j * 64 + fi * 4];
            scS.x  = fmaf(b, aa.x, scS.x);   scS.y  = fmaf(b, aa.y, scS.y);
            scS.z  = fmaf(b, aa.z, scS.z);   scS.w  = fmaf(b, aa.w, scS.w);
            scVx.x = fmaf(bx, bb.x, scVx.x); scVx.y = fmaf(bx, bb.y, scVx.y);
            scVx.z = fmaf(bx, bb.z, scVx.z); scVx.w = fmaf(bx, bb.w, scVx.w);
            scVy.x = fmaf(by, bb.x, scVy.x); scVy.y = fmaf(by, bb.y, scVy.y);
            scVy.z = fmaf(by, bb.z, scVy.z); scVy.w = fmaf(by, bb.w, scVy.w);
            scVz.x = fmaf(bz, bb.x, scVz.x); scVz.y = fmaf(bz, bb.y, scVz.y);
            scVz.z = fmaf(bz, bb.z, scVz.z); scVz.w = fmaf(bz, bb.w, scVz.w);
        }
    }

    const float* pp = pwL + z * 9 * FF;
    float4 P[9];
#pragma unroll
    for (int k = 0; k < 9; k++) P[k] = *(const float4*)&pp[k * FF + fi * 4];
    float4 ps, pvx, pvy, pvz;
#pragma unroll
    for (int c = 0; c < 4; c++) {
        float S  = (&s2.x)[c];
        float VX = (&v2x.x)[c], VY = (&v2y.x)[c], VZ = (&v2z.x)[c];
        float vv = VX * VX + VY * VY + VZ * VZ;
        float S2 = S * S;
        float psv = (&P[0].x)[c] * S + (&P[1].x)[c] * S2 + (&P[2].x)[c] * vv
                  + (&P[3].x)[c] * S2 * S + (&P[4].x)[c] * S * vv;
        float pf  = (&P[5].x)[c] + (&P[6].x)[c] * S + (&P[7].x)[c] * S2 + (&P[8].x)[c] * vv;
        (&ps.x)[c]  = psv;
        (&pvx.x)[c] = pf * VX;
        (&pvy.x)[c] = pf * VY;
        (&pvz.x)[c] = pf * VZ;
    }
    __syncthreads();

    {
        const float4* a4 = (const float4*)WpsL;
        const float4* b4 = (const float4*)WpvL;
        float4* d0 = (float4*)Wb0;
        float4* d1 = (float4*)Wb1;
        for (int i = t; i < 1024; i += 256) { d0[i] = a4[i]; d1[i] = b4[i]; }
    }
    *(float4*)&A_s[nl * 64 + fi * 4] = ps;
    *(float4*)&A_v[(nl * 3 + 0) * 64 + fi * 4] = pvx;
    *(float4*)&A_v[(nl * 3 + 1) * 64 + fi * 4] = pvy;
    *(float4*)&A_v[(nl * 3 + 2) * 64 + fi * 4] = pvz;
    __syncthreads();

    float4 sN  = scS;
    float4 vNx = scVx, vNy = scVy, vNz = scVz;
#pragma unroll 4
    for (int j = 0; j < FF; j++) {
        float a  = A_s[nl * 64 + j];
        float ax = A_v[(nl * 3 + 0) * 64 + j];
        float ay = A_v[(nl * 3 + 1) * 64 + j];
        float az = A_v[(nl * 3 + 2) * 64 + j];
        float4 wps = *(const float4*)&Wb0[j * 64 + fi * 4];
        float4 wpv = *(const float4*)&Wb1[j * 64 + fi * 4];
        sN.x  = fmaf(a, wps.x, sN.x);   sN.y  = fmaf(a, wps.y, sN.y);
        sN.z  = fmaf(a, wps.z, sN.z);   sN.w  = fmaf(a, wps.w, sN.w);
        vNx.x = fmaf(ax, wpv.x, vNx.x); vNx.y = fmaf(ax, wpv.y, vNx.y);
        vNx.z = fmaf(ax, wpv.z, vNx.z); vNx.w = fmaf(ax, wpv.w, vNx.w);
        vNy.x = fmaf(ay, wpv.x, vNy.x); vNy.y = fmaf(ay, wpv.y, vNy.y);
        vNy.z = fmaf(ay, wpv.z, vNy.z); vNy.w = fmaf(ay, wpv.w, vNy.w);
        vNz.x = fmaf(az, wpv.x, vNz.x); vNz.y = fmaf(az, wpv.y, vNz.y);
        vNz.z = fmaf(az, wpv.z, vNz.z); vNz.w = fmaf(az, wpv.w, vNz.w);
    }

    if (LAYER < LL - 1) {
        ((float4*)sNew)[n * 16 + fi] = sN;
        ((float4*)vNew)[(n * 3 + 0) * 16 + fi] = vNx;
        ((float4*)vNew)[(n * 3 + 1) * 16 + fi] = vNy;
        ((float4*)vNew)[(n * 3 + 2) * 16 + fi] = vNz;
    }

    if (LAYER == 0) {
        float4 wr = *(const float4*)&Wread0[fi * 4];
        float part = sN.x * wr.x + sN.y * wr.y + sN.z * wr.z + sN.w * wr.w;
#pragma unroll
        for (int o = 8; o > 0; o >>= 1)
            part += __shfl_xor_sync(0xffffffffu, part, o);
        if (fi == 0) out[n * LL + 0] = part;
    } else {
        *(float4*)&B_s[nl * 64 + fi * 4] = sN;
        __syncthreads();
        int h = fi;
        float a = 0.f;
#pragma unroll 8
        for (int g = 0; g < FF; g++)
            a = fmaf(B_s[nl * 64 + g], Wr1a[g * HH + h], a);
        float sil = a / (1.f + __expf(-a));
        float part = sil * Wr1b[h];
#pragma unroll
        for (int o = 8; o > 0; o >>= 1)
            part += __shfl_xor_sync(0xffffffffu, part, o);
        if (fi == 0) out[n * LL + (LL - 1)] = part;
    }
}

// ---------------------------------------------------------------------------
extern "C" void kernel_launch(void* const* d_in, const int* in_sizes, int n_in,
                              void* d_out, int out_size) {
    const float* vectors = (const float*)d_in[0];
    const float* embed_s = (const float*)d_in[1];
    const float* Wr      = (const float*)d_in[2];
    const float* Wls     = (const float*)d_in[3];
    const float* Wlv     = (const float*)d_in[4];
    const float* skip_s  = (const float*)d_in[5];
    const float* skip_v  = (const float*)d_in[6];
    const float* pw      = (const float*)d_in[7];
    const float* Wps     = (const float*)d_in[8];
    const float* Wpv     = (const float*)d_in[9];
    const float* Wread0  = (const float*)d_in[10];
    const float* Wr1a    = (const float*)d_in[11];
    const float* Wr1b    = (const float*)d_in[12];
    const int*   senders   = (const int*)d_in[13];
    const int*   receivers = (const int*)d_in[14];
    const int*   species   = (const int*)d_in[15];
    float* out = (float*)d_out;

    void *p_sA, *p_vA, *p_sB, *p_vB;
    cudaGetSymbolAddress(&p_sA, g_sA);
    cudaGetSymbolAddress(&p_vA, g_vA);
    cudaGetSymbolAddress(&p_sB, g_sB);
    cudaGetSymbolAddress(&p_vB, g_vB);
    float* sA = (float*)p_sA;
    float* vA = (float*)p_vA;
    float* sB = (float*)p_sB;
    float* vB = (float*)p_vB;

    const int NODE_SMEM = 16384 * 4;  // 64KB
    static bool attrSet = false;
    if (!attrSet) {
        cudaFuncSetAttribute(nodeK<0>, cudaFuncAttributeMaxDynamicSharedMemorySize, NODE_SMEM);
        cudaFuncSetAttribute(nodeK<1>, cudaFuncAttributeMaxDynamicSharedMemorySize, NODE_SMEM);
        attrSet = true;
    }

    initK<<<(NN * FF / 4 + 255) / 256, 256>>>(embed_s, species);

    // ---- Layer 0 ----
    edgeK<true><<<EE / 128, 256>>>(vectors, Wr, senders, receivers, sA, vA);
    nodeK<0><<<NN / 16, 256, NODE_SMEM>>>(sA, vA, sB, vB, species,
                              Wls, Wlv, pw, Wps, Wpv,
                              skip_s, skip_v, Wread0, Wr1a, Wr1b, out);

    // ---- Layer 1 ----
    edgeK<false><<<EE / 128, 256>>>(vectors, Wr + NBB * 5 * FF, senders, receivers, sB, vB);
    nodeK<1><<<NN / 16, 256, NODE_SMEM>>>(sB, vB, sA, vA, species,
                              Wls + FF * FF, Wlv + FF * FF,
                              pw + ZZ * 9 * FF,
                              Wps + FF * FF, Wpv + FF * FF,
                              skip_s, skip_v, Wread0, Wr1a, Wr1b, out);
}

// round 7
// speedup vs baseline: 1.0514x; 1.0502x over previous
#include <cuda_runtime.h>
#include <math.h>

#define NN   32768
#define EE   262144
#define FF   64
#define ZZ   10
#define NBB  8
#define LL   2
#define HH   16

#define EPSC   0.24253562503633297f
#define SQRT2C 1.4142135623730951f
#define PI_F   3.14159265358979323846f

// Scratch (device globals; allocation-free), 16B-aligned for float4 access
__device__ __align__(16) float g_sA[NN * FF];
__device__ __align__(16) float g_vA[NN * 3 * FF];
__device__ __align__(16) float g_sB[NN * FF];
__device__ __align__(16) float g_vB[NN * 3 * FF];
__device__ __align__(16) float g_aggS[NN * FF];
__device__ __align__(16) float g_aggV[NN * 3 * FF];

__device__ __forceinline__ void redAdd1(float* p, float v) {
    asm volatile("red.global.add.f32 [%0], %1;" :: "l"(p), "f"(v) : "memory");
}

// ---------------------------------------------------------------------------
// Init: s = embed_s[spec], v = 0, agg = 0   (float4 wide)
// ---------------------------------------------------------------------------
__global__ void initK(const float* __restrict__ embed, const int* __restrict__ spec) {
    int i = blockIdx.x * 256 + threadIdx.x;
    if (i >= NN * FF / 4) return;
    int n  = i >> 4;
    int f4 = i & 15;
    const float4* e4 = (const float4*)embed;
    ((float4*)g_sA)[i] = e4[spec[n] * 16 + f4];
    float4 z = make_float4(0.f, 0.f, 0.f, 0.f);
    ((float4*)g_aggS)[i] = z;
#pragma unroll
    for (int k = 0; k < 3; k++) {
        ((float4*)g_vA)[(n * 3 + k) * 16 + f4]   = z;
        ((float4*)g_aggV)[(n * 3 + k) * 16 + f4] = z;
    }
}

// ---------------------------------------------------------------------------
// Per-edge scalar staging: bessel basis, unit vector, indices
// ---------------------------------------------------------------------------
__device__ __forceinline__ void stageEdge(
        float (*rb)[32], float (*yv)[32], int* sS, int* rS,
        const float* __restrict__ vec,
        const int* __restrict__ snd, const int* __restrict__ rcv,
        int e, int lane) {
    sS[lane] = snd[e];
    rS[lane] = rcv[e];
    float vx = vec[e * 3 + 0];
    float vy = vec[e * 3 + 1];
    float vz = vec[e * 3 + 2];
    float r  = sqrtf(vx * vx + vy * vy + vz * vz + 1e-12f);
    float rc = fmaxf(r, 1e-6f);
    float env = 0.f;
    if (r < 1.f) {
        float r2 = r * r;
        float r6 = r2 * r2 * r2;
        env = 1.f - 28.f * r6 + 48.f * r6 * r - 21.f * r6 * r2;
    }
    float scale = SQRT2C * env / rc;
    float s1, c1;
    __sincosf(PI_F * rc, &s1, &c1);
    float c2 = 2.f * c1;
    float sp = s1, spp = 0.f;
    rb[0][lane] = s1 * scale;
#pragma unroll
    for (int n = 1; n < NBB; n++) {
        float sn = c2 * sp - spp;
        rb[n][lane] = sn * scale;
        spp = sp; sp = sn;
    }
    float iy = 1.f / r;
    yv[0][lane] = vx * iy; yv[1][lane] = vy * iy; yv[2][lane] = vz * iy;
}

// ---------------------------------------------------------------------------
// Edge kernel v3: 256 threads = 64 channels x 4 edge-lanes.
// Each thread holds its channel's Wr slice in REGISTERS (no per-edge LDS sweep).
// Block processes 128 edges, staged 32 at a time (double buffered); each
// edge-lane consumes 8 edges per stage. rb/y reads are warp-broadcast LDS.
// ---------------------------------------------------------------------------
template <bool FIRST>
__global__ void __launch_bounds__(256) edgeK(
                      const float* __restrict__ vec,
                      const float* __restrict__ WrL,      // [8,320]
                      const int*   __restrict__ snd,
                      const int*   __restrict__ rcv,
                      const float* __restrict__ sIn,      // [N,F]
                      const float* __restrict__ vIn) {    // [N,3,F]
    const int NP = FIRST ? 2 : 5;
    __shared__ float rbS[2][NBB][32];
    __shared__ float yS[2][3][32];
    __shared__ int   sndS[2][32];
    __shared__ int   rcvS[2][32];

    int t  = threadIdx.x;
    int f  = t & 63;
    int el = t >> 6;

    // Wr slice for this channel, in registers (amortized over 128 edges)
    float wreg[NBB][FIRST ? 2 : 5];
#pragma unroll
    for (int n = 0; n < NBB; n++)
#pragma unroll
        for (int pi = 0; pi < NP; pi++) {
            int p = FIRST ? pi * 2 : pi;    // layer-0: only paths 0 and 2
            wreg[n][pi] = WrL[n * 320 + p * 64 + f];
        }

    int base = blockIdx.x * 128;

    if (t < 32)
        stageEdge(rbS[0], yS[0], sndS[0], rcvS[0], vec, snd, rcv, base + t, t);
    __syncthreads();

#pragma unroll
    for (int s = 0; s < 4; s++) {
        int buf = s & 1;
        if (s < 3 && t < 32)
            stageEdge(rbS[buf ^ 1], yS[buf ^ 1], sndS[buf ^ 1], rcvS[buf ^ 1],
                      vec, snd, rcv, base + (s + 1) * 32 + t, t);

        int e0 = el * 8;
#pragma unroll 2
        for (int le = 0; le < 8; le++) {
            int li = e0 + le;
            int s_ = sndS[buf][li];
            int r_ = rcvS[buf][li];

            // w[p] = sum_n rb[n] * wreg[n][p]  (rb: warp-broadcast LDS)
            float w[5];
#pragma unroll
            for (int pi = 0; pi < NP; pi++) w[pi] = 0.f;
#pragma unroll
            for (int n = 0; n < NBB; n++) {
                float rn = rbS[buf][n][li];
#pragma unroll
                for (int pi = 0; pi < NP; pi++)
                    w[pi] = fmaf(rn, wreg[n][pi], w[pi]);
            }

            float y0 = yS[buf][0][li];
            float y1 = yS[buf][1][li];
            float y2 = yS[buf][2][li];
            float ss = sIn[s_ * FF + f];

            float m0, m1x, m1y, m1z;
            if (FIRST) {
                m0 = w[0] * ss;
                float cc = w[1] * ss;           // path 2 weight
                m1x = cc * y0; m1y = cc * y1; m1z = cc * y2;
            } else {
                float vsx = vIn[(s_ * 3 + 0) * FF + f];
                float vsy = vIn[(s_ * 3 + 1) * FF + f];
                float vsz = vIn[(s_ * 3 + 2) * FF + f];
                float dot = vsx * y0 + vsy * y1 + vsz * y2;
                m0 = w[0] * ss + w[1] * dot;
                float cc = w[2] * ss;
                m1x = cc * y0 + w[3] * vsx + w[4] * (vsy * y2 - vsz * y1);
                m1y = cc * y1 + w[3] * vsy + w[4] * (vsz * y0 - vsx * y2);
                m1z = cc * y2 + w[3] * vsz + w[4] * (vsx * y1 - vsy * y0);
            }

            redAdd1(&g_aggS[r_ * FF + f], m0);
            redAdd1(&g_aggV[(r_ * 3 + 0) * FF + f], m1x);
            redAdd1(&g_aggV[(r_ * 3 + 1) * FF + f], m1y);
            redAdd1(&g_aggV[(r_ * 3 + 2) * FF + f], m1z);
        }
        __syncthreads();
    }
}

// ---------------------------------------------------------------------------
// Node kernel: 16 nodes/block x 16 threads/node (4 channels each, float4)
// ---------------------------------------------------------------------------
template <int LAYER>
__global__ void nodeK(const float* __restrict__ sOld,
                      const float* __restrict__ vOld,
                      float* __restrict__ sNew,
                      float* __restrict__ vNew,
                      const int*   __restrict__ spec,
                      const float* __restrict__ WlsL,
                      const float* __restrict__ WlvL,
                      const float* __restrict__ pwL,    // [Z,9,F]
                      const float* __restrict__ WpsL,
                      const float* __restrict__ WpvL,
                      const float* __restrict__ skipS,  // [Z,F,F]
                      const float* __restrict__ skipV,
                      const float* __restrict__ Wread0,
                      const float* __restrict__ Wr1a,   // [F,H]
                      const float* __restrict__ Wr1b,   // [H]
                      float* __restrict__ out) {
    extern __shared__ float sm[];
    float* Wb0 = sm;                 // 4096
    float* Wb1 = sm + 4096;          // 4096
    float* A_s = sm + 8192;          // 1024
    float* A_v = sm + 9216;          // 3072
    float* B_s = sm + 12288;         // 1024
    float* B_v = sm + 13312;         // 3072  (total 16384 floats = 64KB)

    int t  = threadIdx.x;
    int nl = t >> 4;
    int fi = t & 15;
    int n  = blockIdx.x * 16 + nl;

    {
        const float4* a4 = (const float4*)WlsL;
        const float4* b4 = (const float4*)WlvL;
        float4* d0 = (float4*)Wb0;
        float4* d1 = (float4*)Wb1;
        for (int i = t; i < 1024; i += 256) { d0[i] = a4[i]; d1[i] = b4[i]; }
    }
    {
        float4 a = ((const float4*)g_aggS)[n * 16 + fi];
        a.x *= EPSC; a.y *= EPSC; a.z *= EPSC; a.w *= EPSC;
        *(float4*)&A_s[nl * 64 + fi * 4] = a;
#pragma unroll
        for (int k = 0; k < 3; k++) {
            float4 v = ((const float4*)g_aggV)[(n * 3 + k) * 16 + fi];
            v.x *= EPSC; v.y *= EPSC; v.z *= EPSC; v.w *= EPSC;
            *(float4*)&A_v[(nl * 3 + k) * 64 + fi * 4] = v;
        }
        float4 z = make_float4(0.f, 0.f, 0.f, 0.f);
        if (LAYER == 0) {
            ((float4*)g_aggS)[n * 16 + fi] = z;
#pragma unroll
            for (int k = 0; k < 3; k++) ((float4*)g_aggV)[(n * 3 + k) * 16 + fi] = z;
        }
        if (LAYER > 0) {
            *(float4*)&B_s[nl * 64 + fi * 4] = ((const float4*)sOld)[n * 16 + fi];
#pragma unroll
            for (int k = 0; k < 3; k++)
                *(float4*)&B_v[(nl * 3 + k) * 64 + fi * 4] =
                    ((const float4*)vOld)[(n * 3 + k) * 16 + fi];
        }
    }
    __syncthreads();

    float4 s2  = make_float4(0.f, 0.f, 0.f, 0.f);
    float4 v2x = s2, v2y = s2, v2z = s2;
#pragma unroll 4
    for (int j = 0; j < FF; j++) {
        float a  = A_s[nl * 64 + j];
        float ax = A_v[(nl * 3 + 0) * 64 + j];
        float ay = A_v[(nl * 3 + 1) * 64 + j];
        float az = A_v[(nl * 3 + 2) * 64 + j];
        float4 wls = *(const float4*)&Wb0[j * 64 + fi * 4];
        float4 wlv = *(const float4*)&Wb1[j * 64 + fi * 4];
        s2.x  = fmaf(a, wls.x, s2.x);   s2.y  = fmaf(a, wls.y, s2.y);
        s2.z  = fmaf(a, wls.z, s2.z);   s2.w  = fmaf(a, wls.w, s2.w);
        v2x.x = fmaf(ax, wlv.x, v2x.x); v2x.y = fmaf(ax, wlv.y, v2x.y);
        v2x.z = fmaf(ax, wlv.z, v2x.z); v2x.w = fmaf(ax, wlv.w, v2x.w);
        v2y.x = fmaf(ay, wlv.x, v2y.x); v2y.y = fmaf(ay, wlv.y, v2y.y);
        v2y.z = fmaf(ay, wlv.z, v2y.z); v2y.w = fmaf(ay, wlv.w, v2y.w);
        v2z.x = fmaf(az, wlv.x, v2z.x); v2z.y = fmaf(az, wlv.y, v2z.y);
        v2z.z = fmaf(az, wlv.z, v2z.z); v2z.w = fmaf(az, wlv.w, v2z.w);
    }

    int z = spec[n];

    float4 scS  = make_float4(0.f, 0.f, 0.f, 0.f);
    float4 scVx = scS, scVy = scS, scVz = scS;
    if (LAYER > 0) {
        const float* Ss = skipS + z * FF * FF;
        const float* Sv = skipV + z * FF * FF;
#pragma unroll 4
        for (int j = 0; j < FF; j++) {
            float b  = B_s[nl * 64 + j];
            float bx = B_v[(nl * 3 + 0) * 64 + j];
            float by = B_v[(nl * 3 + 1) * 64 + j];
            float bz = B_v[(nl * 3 + 2) * 64 + j];
            float4 aa = *(const float4*)&Ss[j * 64 + fi * 4];
            float4 bb = *(const float4*)&Sv[j * 64 + fi * 4];
            scS.x  = fmaf(b, aa.x, scS.x);   scS.y  = fmaf(b, aa.y, scS.y);
            scS.z  = fmaf(b, aa.z, scS.z);   scS.w  = fmaf(b, aa.w, scS.w);
            scVx.x = fmaf(bx, bb.x, scVx.x); scVx.y = fmaf(bx, bb.y, scVx.y);
            scVx.z = fmaf(bx, bb.z, scVx.z); scVx.w = fmaf(bx, bb.w, scVx.w);
            scVy.x = fmaf(by, bb.x, scVy.x); scVy.y = fmaf(by, bb.y, scVy.y);
            scVy.z = fmaf(by, bb.z, scVy.z); scVy.w = fmaf(by, bb.w, scVy.w);
            scVz.x = fmaf(bz, bb.x, scVz.x); scVz.y = fmaf(bz, bb.y, scVz.y);
            scVz.z = fmaf(bz, bb.z, scVz.z); scVz.w = fmaf(bz, bb.w, scVz.w);
        }
    }

    const float* pp = pwL + z * 9 * FF;
    float4 P[9];
#pragma unroll
    for (int k = 0; k < 9; k++) P[k] = *(const float4*)&pp[k * FF + fi * 4];
    float4 ps, pvx, pvy, pvz;
#pragma unroll
    for (int c = 0; c < 4; c++) {
        float S  = (&s2.x)[c];
        float VX = (&v2x.x)[c], VY = (&v2y.x)[c], VZ = (&v2z.x)[c];
        float vv = VX * VX + VY * VY + VZ * VZ;
        float S2 = S * S;
        float psv = (&P[0].x)[c] * S + (&P[1].x)[c] * S2 + (&P[2].x)[c] * vv
                  + (&P[3].x)[c] * S2 * S + (&P[4].x)[c] * S * vv;
        float pf  = (&P[5].x)[c] + (&P[6].x)[c] * S + (&P[7].x)[c] * S2 + (&P[8].x)[c] * vv;
        (&ps.x)[c]  = psv;
        (&pvx.x)[c] = pf * VX;
        (&pvy.x)[c] = pf * VY;
        (&pvz.x)[c] = pf * VZ;
    }
    __syncthreads();

    {
        const float4* a4 = (const float4*)WpsL;
        const float4* b4 = (const float4*)WpvL;
        float4* d0 = (float4*)Wb0;
        float4* d1 = (float4*)Wb1;
        for (int i = t; i < 1024; i += 256) { d0[i] = a4[i]; d1[i] = b4[i]; }
    }
    *(float4*)&A_s[nl * 64 + fi * 4] = ps;
    *(float4*)&A_v[(nl * 3 + 0) * 64 + fi * 4] = pvx;
    *(float4*)&A_v[(nl * 3 + 1) * 64 + fi * 4] = pvy;
    *(float4*)&A_v[(nl * 3 + 2) * 64 + fi * 4] = pvz;
    __syncthreads();

    float4 sN  = scS;
    float4 vNx = scVx, vNy = scVy, vNz = scVz;
#pragma unroll 4
    for (int j = 0; j < FF; j++) {
        float a  = A_s[nl * 64 + j];
        float ax = A_v[(nl * 3 + 0) * 64 + j];
        float ay = A_v[(nl * 3 + 1) * 64 + j];
        float az = A_v[(nl * 3 + 2) * 64 + j];
        float4 wps = *(const float4*)&Wb0[j * 64 + fi * 4];
        float4 wpv = *(const float4*)&Wb1[j * 64 + fi * 4];
        sN.x  = fmaf(a, wps.x, sN.x);   sN.y  = fmaf(a, wps.y, sN.y);
        sN.z  = fmaf(a, wps.z, sN.z);   sN.w  = fmaf(a, wps.w, sN.w);
        vNx.x = fmaf(ax, wpv.x, vNx.x); vNx.y = fmaf(ax, wpv.y, vNx.y);
        vNx.z = fmaf(ax, wpv.z, vNx.z); vNx.w = fmaf(ax, wpv.w, vNx.w);
        vNy.x = fmaf(ay, wpv.x, vNy.x); vNy.y = fmaf(ay, wpv.y, vNy.y);
        vNy.z = fmaf(ay, wpv.z, vNy.z); vNy.w = fmaf(ay, wpv.w, vNy.w);
        vNz.x = fmaf(az, wpv.x, vNz.x); vNz.y = fmaf(az, wpv.y, vNz.y);
        vNz.z = fmaf(az, wpv.z, vNz.z); vNz.w = fmaf(az, wpv.w, vNz.w);
    }

    if (LAYER < LL - 1) {
        ((float4*)sNew)[n * 16 + fi] = sN;
        ((float4*)vNew)[(n * 3 + 0) * 16 + fi] = vNx;
        ((float4*)vNew)[(n * 3 + 1) * 16 + fi] = vNy;
        ((float4*)vNew)[(n * 3 + 2) * 16 + fi] = vNz;
    }

    if (LAYER == 0) {
        float4 wr = *(const float4*)&Wread0[fi * 4];
        float part = sN.x * wr.x + sN.y * wr.y + sN.z * wr.z + sN.w * wr.w;
#pragma unroll
        for (int o = 8; o > 0; o >>= 1)
            part += __shfl_xor_sync(0xffffffffu, part, o);
        if (fi == 0) out[n * LL + 0] = part;
    } else {
        *(float4*)&B_s[nl * 64 + fi * 4] = sN;
        __syncthreads();
        int h = fi;
        float a = 0.f;
#pragma unroll 8
        for (int g = 0; g < FF; g++)
            a = fmaf(B_s[nl * 64 + g], Wr1a[g * HH + h], a);
        float sil = a / (1.f + __expf(-a));
        float part = sil * Wr1b[h];
#pragma unroll
        for (int o = 8; o > 0; o >>= 1)
            part += __shfl_xor_sync(0xffffffffu, part, o);
        if (fi == 0) out[n * LL + (LL - 1)] = part;
    }
}

// ---------------------------------------------------------------------------
extern "C" void kernel_launch(void* const* d_in, const int* in_sizes, int n_in,
                              void* d_out, int out_size) {
    const float* vectors = (const float*)d_in[0];
    const float* embed_s = (const float*)d_in[1];
    const float* Wr      = (const float*)d_in[2];
    const float* Wls     = (const float*)d_in[3];
    const float* Wlv     = (const float*)d_in[4];
    const float* skip_s  = (const float*)d_in[5];
    const float* skip_v  = (const float*)d_in[6];
    const float* pw      = (const float*)d_in[7];
    const float* Wps     = (const float*)d_in[8];
    const float* Wpv     = (const float*)d_in[9];
    const float* Wread0  = (const float*)d_in[10];
    const float* Wr1a    = (const float*)d_in[11];
    const float* Wr1b    = (const float*)d_in[12];
    const int*   senders   = (const int*)d_in[13];
    const int*   receivers = (const int*)d_in[14];
    const int*   species   = (const int*)d_in[15];
    float* out = (float*)d_out;

    void *p_sA, *p_vA, *p_sB, *p_vB;
    cudaGetSymbolAddress(&p_sA, g_sA);
    cudaGetSymbolAddress(&p_vA, g_vA);
    cudaGetSymbolAddress(&p_sB, g_sB);
    cudaGetSymbolAddress(&p_vB, g_vB);
    float* sA = (float*)p_sA;
    float* vA = (float*)p_vA;
    float* sB = (float*)p_sB;
    float* vB = (float*)p_vB;

    const int NODE_SMEM = 16384 * 4;  // 64KB
    static bool attrSet = false;
    if (!attrSet) {
        cudaFuncSetAttribute(nodeK<0>, cudaFuncAttributeMaxDynamicSharedMemorySize, NODE_SMEM);
        cudaFuncSetAttribute(nodeK<1>, cudaFuncAttributeMaxDynamicSharedMemorySize, NODE_SMEM);
        attrSet = true;
    }

    initK<<<(NN * FF / 4 + 255) / 256, 256>>>(embed_s, species);

    // ---- Layer 0 ----
    edgeK<true><<<EE / 128, 256>>>(vectors, Wr, senders, receivers, sA, vA);
    nodeK<0><<<NN / 16, 256, NODE_SMEM>>>(sA, vA, sB, vB, species,
                              Wls, Wlv, pw, Wps, Wpv,
                              skip_s, skip_v, Wread0, Wr1a, Wr1b, out);

    // ---- Layer 1 ----
    edgeK<false><<<EE / 128, 256>>>(vectors, Wr + NBB * 5 * FF, senders, receivers, sB, vB);
    nodeK<1><<<NN / 16, 256, NODE_SMEM>>>(sB, vB, sA, vA, species,
                              Wls + FF * FF, Wlv + FF * FF,
                              pw + ZZ * 9 * FF,
                              Wps + FF * FF, Wpv + FF * FF,
                              skip_s, skip_v, Wread0, Wr1a, Wr1b, out);
}